// round 16
// baseline (speedup 1.0000x reference)
#include <cuda_runtime.h>
#include <cuda_fp16.h>
#include <cstdint>

#define NP 8192
#define NG 128
#define NGNG (NG * NG)
#define KSPLIT 128
#define KSLICE 64
#define NSPLIT2 8
#define H2_PER_SLICE (3 * NGNG / 2)   // 24576 half2 per slice
#define NT 1024

// smem byte offsets (dynamic, 64KB): A + 3 channel B tables, all fp16
#define A_T 0
#define B_T(ch) (16384 + (ch) * 16384)
#define SMEM_TOTAL 65536

// Partials in fragment order, fp16: [ks][ch][j] (half2), 12 MB
__device__ __half2 g_parth[KSPLIT * H2_PER_SLICE];
// Stage-1 output: [s][ch*8192 + j] as float2, 1.5 MB
__device__ float2 g_p2[NSPLIT2 * H2_PER_SLICE];
// Monotonic grid-barrier counters (never reset -> deterministic across replays)
__device__ unsigned g_bar1 = 0, g_bar2 = 0;

#define SWZ(o) ((o) ^ (((o) >> 3) & 0x70))

__device__ __forceinline__ uint32_t smem_u32(const void* p) {
    uint32_t a;
    asm("{ .reg .u64 t; cvta.to.shared.u64 t, %1; cvt.u32.u64 %0, t; }"
        : "=r"(a) : "l"(p));
    return a;
}
__device__ __forceinline__ void ldsm4(uint32_t& r0, uint32_t& r1,
                                      uint32_t& r2, uint32_t& r3, uint32_t a) {
    asm volatile("ldmatrix.sync.aligned.m8n8.x4.shared.b16 {%0,%1,%2,%3}, [%4];"
                 : "=r"(r0), "=r"(r1), "=r"(r2), "=r"(r3) : "r"(a));
}
__device__ __forceinline__ void mma16816(float* d, const uint32_t* a,
                                         const uint32_t* b) {
    asm volatile(
        "mma.sync.aligned.m16n8k16.row.col.f32.f16.f16.f32 "
        "{%0,%1,%2,%3},{%4,%5,%6,%7},{%8,%9},{%0,%1,%2,%3};"
        : "+f"(d[0]), "+f"(d[1]), "+f"(d[2]), "+f"(d[3])
        : "r"(a[0]), "r"(a[1]), "r"(a[2]), "r"(a[3]), "r"(b[0]), "r"(b[1]));
}
__device__ __forceinline__ uint32_t pack_f16(float a, float b) {
    __half2 h = __floats2half2_rn(a, b);
    return *(uint32_t*)&h;
}

// All 128 blocks co-resident (1 block/SM) -> spin is deadlock-free.
// Monotonic count -> deterministic across graph replays.
__device__ __forceinline__ void grid_barrier(unsigned* cnt) {
    __syncthreads();
    if (threadIdx.x == 0) {
        __threadfence();
        unsigned old = atomicAdd(cnt, 1);
        unsigned target = (old / gridDim.x + 1) * gridDim.x;
        unsigned v;
        do {
            asm volatile("ld.acquire.gpu.u32 %0, [%1];" : "=r"(v) : "l"(cnt));
            if (v >= target) break;
            __nanosleep(64);
        } while (true);
    }
    __syncthreads();
}

// ---------------------------------------------------------------------------
// Fused kernel: fp16 GEMM partials -> barrier -> reduce1 -> barrier -> reduce2.
// Grid 128 x 1024 threads (32 warps/SM), one wave.
// Warp grid 8m x 4n, warp tile 16x32.
// ---------------------------------------------------------------------------
__global__ void __launch_bounds__(NT, 1) fused_kernel(
    const float* __restrict__ X, const float* __restrict__ Y,
    float* __restrict__ out) {
    extern __shared__ char smem[];
    uint32_t sb = smem_u32(smem);
    int tid = threadIdx.x, lane = tid & 31, wid = tid >> 5;
    int ks = blockIdx.x;
    int kbeg = ks * KSLICE;

    const float GSTEP = 4.0f / 127.0f;
    const float4* Xq = (const float4*)X;     // one float4 = two (x,y) points
    const float4* Yq = (const float4*)Y;

    // ================= Phase 1: GEMM partials ===============================
    // ---- Build A: Ex[m][k] fp16, k-pairs packed, SW128 rows ---------------
    #pragma unroll
    for (int it = 0; it < 4; it++) {
        int idx = it * NT + tid;             // 4096 items: 128 m x 32 kpairs
        int kp = idx & 31, m = idx >> 5;
        int kk = 2 * kp;
        float4 xq = Xq[(kbeg + kk) >> 1];
        float gm = fmaf((float)m, GSTEP, -2.0f);
        float d0 = gm - xq.x, d1 = gm - xq.z;
        float e0 = __expf(-0.5f * d0 * d0);
        float e1 = __expf(-0.5f * d1 * d1);
        uint32_t sw = SWZ((uint32_t)(m * 128 + kk * 2));
        *(uint32_t*)(smem + A_T + sw) = pack_f16(e0, e1);
    }
    // ---- Build B: ey once, 3 channel fp16 tables ---------------------------
    #pragma unroll
    for (int it = 0; it < 4; it++) {
        int idx = it * NT + tid;             // 4096 items: 128 n x 32 kpairs
        int kp = idx & 31, n = idx >> 5;
        int kk = 2 * kp;
        float4 xq = Xq[(kbeg + kk) >> 1];
        float4 yq = Yq[(kbeg + kk) >> 1];
        float gn = fmaf((float)n, GSTEP, -2.0f);
        float d0 = gn - xq.y, d1 = gn - xq.w;
        float e0 = __expf(-0.5f * d0 * d0);
        float e1 = __expf(-0.5f * d1 * d1);
        uint32_t sw = SWZ((uint32_t)(n * 128 + kk * 2));
        *(uint32_t*)(smem + B_T(0) + sw) = pack_f16(e0, e1);
        *(uint32_t*)(smem + B_T(1) + sw) = pack_f16(e0 * yq.x, e1 * yq.z);
        *(uint32_t*)(smem + B_T(2) + sw) = pack_f16(e0 * yq.y, e1 * yq.w);
    }
    __syncthreads();

    // ---- Warp tiling: 8 m-warps x 4 n-warps, warp tile 16x32 --------------
    int wm = (wid & 7) * 16, wn = (wid >> 3) * 32;
    int arow = lane & 15;
    uint32_t acolx = (uint32_t)((lane >> 4) << 4);
    int brow = (lane & 7) + ((lane & 16) ? 8 : 0);
    uint32_t bcolx = (lane & 8) ? 16u : 0u;
    uint32_t axor = (uint32_t)((arow & 7) << 4);
    uint32_t bxor = (uint32_t)((lane & 7) << 4);

    uint32_t ab0 = sb + A_T + (uint32_t)((wm + arow) * 128);

    // ---- Hoist A fragments once (shared by all 3 channels) ----------------
    uint32_t afr[4][4];
    #pragma unroll
    for (int kstep = 0; kstep < 4; kstep++) {
        uint32_t acol = (uint32_t)(kstep * 32 + acolx) ^ axor;
        ldsm4(afr[kstep][0], afr[kstep][1], afr[kstep][2], afr[kstep][3],
              ab0 + acol);
    }

    #pragma unroll 1
    for (int ch = 0; ch < 3; ch++) {
        float acc[4][4];
        #pragma unroll
        for (int j = 0; j < 4; j++)
            #pragma unroll
            for (int c = 0; c < 4; c++) acc[j][c] = 0.0f;

        uint32_t bb0 = sb + B_T(ch) + (uint32_t)((wn + brow) * 128);
        uint32_t bb1 = sb + B_T(ch) + (uint32_t)((wn + 16 + brow) * 128);

        #pragma unroll
        for (int kstep = 0; kstep < 4; kstep++) {
            uint32_t bcol = (uint32_t)(kstep * 32 + bcolx) ^ bxor;
            uint32_t bf[4][2];
            ldsm4(bf[0][0], bf[0][1], bf[1][0], bf[1][1], bb0 + bcol);
            ldsm4(bf[2][0], bf[2][1], bf[3][0], bf[3][1], bb1 + bcol);
            #pragma unroll
            for (int nt = 0; nt < 4; nt++)
                mma16816(acc[nt], afr[kstep], bf[nt]);
        }

        // Epilogue: fragment-order, coalesced uint2 stores
        // j = nt*2048 + tid*2 + (c>>1), comp = c&1
        __half2* base = g_parth + (ks * 3 + ch) * (NGNG / 2);
        #pragma unroll
        for (int nt = 0; nt < 4; nt++) {
            __half2 p01 = __floats2half2_rn(acc[nt][0], acc[nt][1]);
            __half2 p23 = __floats2half2_rn(acc[nt][2], acc[nt][3]);
            uint2 pk = make_uint2(*(uint32_t*)&p01, *(uint32_t*)&p23);
            *(uint2*)(base + nt * 2048 + tid * 2) = pk;
        }
    }

    // ================= Phase 2: reduce stage 1 (MLP=16) =====================
    grid_barrier(&g_bar1);

    int gid = blockIdx.x * NT + tid;         // 0 .. 131071
    #pragma unroll
    for (int t = 0; t < 2; t++) {
        int task = t * 131072 + gid;         // 196608 tasks total
        if (t == 1 && task >= 196608) break;
        int s = task / 24576;                // split 0..7
        int j = task - s * 24576;            // half2 lane 0..24575
        const __half2* p = g_parth + (s * 16) * H2_PER_SLICE + j;
        float2 v[16];
        #pragma unroll
        for (int k = 0; k < 16; k++)
            v[k] = __half22float2(p[k * H2_PER_SLICE]);
        float sx = 0.0f, sy = 0.0f;
        #pragma unroll
        for (int k = 0; k < 16; k++) { sx += v[k].x; sy += v[k].y; }
        g_p2[s * H2_PER_SLICE + j] = make_float2(sx, sy);
    }

    // ================= Phase 3: reduce stage 2 (all 128 blocks) =============
    grid_barrier(&g_bar2);

    if (tid < 128) {
        int g = blockIdx.x * 128 + tid;
        int m = g & 127, n = g >> 7;
        // Inverse of the fragment mapping:
        // m = (wid&7)*16 + quad + 8*(c>>1), n = (wid>>3)*32 + nt*8 + 2tq + (c&1)
        int wid2 = (m >> 4) | ((n >> 5) << 3);
        int quad = m & 7;
        int cr = (m >> 3) & 1;
        int nt = (n >> 3) & 3;
        int tq = (n >> 1) & 3;
        int comp = n & 1;
        int tidm = wid2 * 32 + quad * 4 + tq;
        int j = nt * 2048 + tidm * 2 + cr;

        float t[3];
        #pragma unroll
        for (int ch = 0; ch < 3; ch++) {
            int jj = ch * (NGNG / 2) + j;
            float2 v[NSPLIT2];
            #pragma unroll
            for (int sp = 0; sp < NSPLIT2; sp++)
                v[sp] = g_p2[sp * H2_PER_SLICE + jj];
            float s = 0.0f;
            #pragma unroll
            for (int sp = 0; sp < NSPLIT2; sp++)
                s += comp ? v[sp].y : v[sp].x;
            t[ch] = s;
        }
        float inv = 1.0f / t[0];
        out[g]            = t[0];
        out[NGNG + g]     = t[1] * inv;
        out[2 * NGNG + g] = t[2] * inv;
    }
}

extern "C" void kernel_launch(void* const* d_in, const int* in_sizes, int n_in,
                              void* d_out, int out_size) {
    const float* X = (const float*)d_in[0];
    const float* Y = (const float*)d_in[1];
    float* out = (float*)d_out;

    cudaFuncSetAttribute(fused_kernel,
                         cudaFuncAttributeMaxDynamicSharedMemorySize, SMEM_TOTAL);
    fused_kernel<<<KSPLIT, NT, SMEM_TOTAL>>>(X, Y, out);
}

// round 17
// speedup vs baseline: 1.1604x; 1.1604x over previous
#include <cuda_runtime.h>
#include <cuda_fp16.h>
#include <cstdint>

#define NP 8192
#define NG 128
#define NGNG (NG * NG)
#define KSPLIT 128
#define KSLICE 64
#define H2_PER_CH 8192                 // half2 lanes per channel per slice
#define H2_PER_SLICE (3 * H2_PER_CH)   // 24576 half2 per slice

// smem byte offsets (dynamic, 64KB): A + 3 channel B tables, all fp16
#define A_T 0
#define B_T(ch) (16384 + (ch) * 16384)
#define SMEM_TOTAL 65536

// Partials in fragment order, fp16: [ks][ch][j] (half2), 12 MB
__device__ __half2 g_parth[KSPLIT * H2_PER_SLICE];
// Monotonic grid-barrier counter (never reset -> deterministic across replays)
__device__ unsigned g_bar1 = 0;

#define SWZ(o) ((o) ^ (((o) >> 3) & 0x70))

__device__ __forceinline__ uint32_t smem_u32(const void* p) {
    uint32_t a;
    asm("{ .reg .u64 t; cvta.to.shared.u64 t, %1; cvt.u32.u64 %0, t; }"
        : "=r"(a) : "l"(p));
    return a;
}
__device__ __forceinline__ void ldsm4(uint32_t& r0, uint32_t& r1,
                                      uint32_t& r2, uint32_t& r3, uint32_t a) {
    asm volatile("ldmatrix.sync.aligned.m8n8.x4.shared.b16 {%0,%1,%2,%3}, [%4];"
                 : "=r"(r0), "=r"(r1), "=r"(r2), "=r"(r3) : "r"(a));
}
__device__ __forceinline__ void mma16816(float* d, const uint32_t* a,
                                         const uint32_t* b) {
    asm volatile(
        "mma.sync.aligned.m16n8k16.row.col.f32.f16.f16.f32 "
        "{%0,%1,%2,%3},{%4,%5,%6,%7},{%8,%9},{%0,%1,%2,%3};"
        : "+f"(d[0]), "+f"(d[1]), "+f"(d[2]), "+f"(d[3])
        : "r"(a[0]), "r"(a[1]), "r"(a[2]), "r"(a[3]), "r"(b[0]), "r"(b[1]));
}
__device__ __forceinline__ uint32_t pack_f16(float a, float b) {
    __half2 h = __floats2half2_rn(a, b);
    return *(uint32_t*)&h;
}

// All 128 blocks co-resident (1 block/SM) -> spin is deadlock-free.
// Monotonic count -> deterministic across graph replays.
__device__ __forceinline__ void grid_barrier(unsigned* cnt) {
    __syncthreads();
    if (threadIdx.x == 0) {
        __threadfence();
        unsigned old = atomicAdd(cnt, 1);
        unsigned target = (old / gridDim.x + 1) * gridDim.x;
        unsigned v;
        do {
            asm volatile("ld.acquire.gpu.u32 %0, [%1];" : "=r"(v) : "l"(cnt));
            if (v >= target) break;
            __nanosleep(64);
        } while (true);
    }
    __syncthreads();
}

// ---------------------------------------------------------------------------
// Fused kernel: fp16 GEMM partials -> ONE grid barrier -> single-phase
// reduce + normalize + write. Grid 128 x 512 threads, one wave.
// ---------------------------------------------------------------------------
__global__ void __launch_bounds__(512, 1) fused_kernel(
    const float* __restrict__ X, const float* __restrict__ Y,
    float* __restrict__ out) {
    extern __shared__ char smem[];
    uint32_t sb = smem_u32(smem);
    int tid = threadIdx.x, lane = tid & 31, wid = tid >> 5;
    int ks = blockIdx.x;
    int kbeg = ks * KSLICE;

    const float GSTEP = 4.0f / 127.0f;
    const float4* Xq = (const float4*)X;     // one float4 = two (x,y) points
    const float4* Yq = (const float4*)Y;

    // ================= Phase 1: GEMM partials (R15-verified) ================
    #pragma unroll
    for (int it = 0; it < 8; it++) {
        int idx = it * 512 + tid;            // 4096 items: 128 m x 32 kpairs
        int kp = idx & 31, m = idx >> 5;
        int kk = 2 * kp;
        float4 xq = Xq[(kbeg + kk) >> 1];
        float gm = fmaf((float)m, GSTEP, -2.0f);
        float d0 = gm - xq.x, d1 = gm - xq.z;
        float e0 = __expf(-0.5f * d0 * d0);
        float e1 = __expf(-0.5f * d1 * d1);
        uint32_t sw = SWZ((uint32_t)(m * 128 + kk * 2));
        *(uint32_t*)(smem + A_T + sw) = pack_f16(e0, e1);
    }
    #pragma unroll
    for (int it = 0; it < 8; it++) {
        int idx = it * 512 + tid;            // 4096 items: 128 n x 32 kpairs
        int kp = idx & 31, n = idx >> 5;
        int kk = 2 * kp;
        float4 xq = Xq[(kbeg + kk) >> 1];
        float4 yq = Yq[(kbeg + kk) >> 1];
        float gn = fmaf((float)n, GSTEP, -2.0f);
        float d0 = gn - xq.y, d1 = gn - xq.w;
        float e0 = __expf(-0.5f * d0 * d0);
        float e1 = __expf(-0.5f * d1 * d1);
        uint32_t sw = SWZ((uint32_t)(n * 128 + kk * 2));
        *(uint32_t*)(smem + B_T(0) + sw) = pack_f16(e0, e1);
        *(uint32_t*)(smem + B_T(1) + sw) = pack_f16(e0 * yq.x, e1 * yq.z);
        *(uint32_t*)(smem + B_T(2) + sw) = pack_f16(e0 * yq.y, e1 * yq.w);
    }
    __syncthreads();

    int wm = (wid & 3) * 32, wn = (wid >> 2) * 32;
    int arow = lane & 15;
    uint32_t acolx = (uint32_t)((lane >> 4) << 4);
    int brow = (lane & 7) + ((lane & 16) ? 8 : 0);
    uint32_t bcolx = (lane & 8) ? 16u : 0u;
    uint32_t axor = (uint32_t)((arow & 7) << 4);
    uint32_t bxor = (uint32_t)((lane & 7) << 4);

    uint32_t ab0 = sb + A_T + (uint32_t)((wm + arow) * 128);
    uint32_t ab1 = ab0 + 16 * 128;

    // Hoist A fragments once (shared by all 3 channels)
    uint32_t afr[4][8];
    #pragma unroll
    for (int kstep = 0; kstep < 4; kstep++) {
        uint32_t acol = (uint32_t)(kstep * 32 + acolx) ^ axor;
        ldsm4(afr[kstep][0], afr[kstep][1], afr[kstep][2], afr[kstep][3], ab0 + acol);
        ldsm4(afr[kstep][4], afr[kstep][5], afr[kstep][6], afr[kstep][7], ab1 + acol);
    }

    #pragma unroll 1
    for (int ch = 0; ch < 3; ch++) {
        float acc[2][4][4];
        #pragma unroll
        for (int i = 0; i < 2; i++)
            #pragma unroll
            for (int j = 0; j < 4; j++)
                #pragma unroll
                for (int c = 0; c < 4; c++) acc[i][j][c] = 0.0f;

        uint32_t bb0 = sb + B_T(ch) + (uint32_t)((wn + brow) * 128);
        uint32_t bb1 = sb + B_T(ch) + (uint32_t)((wn + 16 + brow) * 128);

        #pragma unroll
        for (int kstep = 0; kstep < 4; kstep++) {
            uint32_t bcol = (uint32_t)(kstep * 32 + bcolx) ^ bxor;
            uint32_t bf[4][2];
            ldsm4(bf[0][0], bf[0][1], bf[1][0], bf[1][1], bb0 + bcol);
            ldsm4(bf[2][0], bf[2][1], bf[3][0], bf[3][1], bb1 + bcol);
            #pragma unroll
            for (int nt = 0; nt < 4; nt++) {
                mma16816(acc[0][nt], &afr[kstep][0], bf[nt]);
                mma16816(acc[1][nt], &afr[kstep][4], bf[nt]);
            }
        }

        // Epilogue: fragment order. half2 index = (mt*4+nt)*1024 + tid*2 + p
        __half2* base = g_parth + (ks * 3 + ch) * H2_PER_CH;
        #pragma unroll
        for (int mt = 0; mt < 2; mt++) {
            #pragma unroll
            for (int nt = 0; nt < 4; nt++) {
                __half2 p01 = __floats2half2_rn(acc[mt][nt][0], acc[mt][nt][1]);
                __half2 p23 = __floats2half2_rn(acc[mt][nt][2], acc[mt][nt][3]);
                uint2 pk = make_uint2(*(uint32_t*)&p01, *(uint32_t*)&p23);
                *(uint2*)(base + ((mt * 4 + nt) << 10) + tid * 2) = pk;
            }
        }
    }

    // ================= Phase 2: single-phase reduce + normalize =============
    grid_barrier(&g_bar1);

    // Block ks owns j in [64*ks, 64*ks+64). Thread = (jj 0..63, sp 0..7):
    // sums 3 channels x 16 slices for one half2 lane.
    float* red = (float*)smem;               // [3][8][64][2] = 3072 floats
    {
        int jj = tid & 63, sp = tid >> 6;
        int j = ks * 64 + jj;
        uint32_t raw[3][16];
        #pragma unroll
        for (int ch = 0; ch < 3; ch++) {
            const uint32_t* p = (const uint32_t*)(g_parth
                + ((sp * 16) * 3 + ch) * H2_PER_CH + j);
            #pragma unroll
            for (int k = 0; k < 16; k++)     // 16 independent L2 loads
                raw[ch][k] = p[k * H2_PER_SLICE];
        }
        #pragma unroll
        for (int ch = 0; ch < 3; ch++) {
            float sx = 0.0f, sy = 0.0f;
            #pragma unroll
            for (int k = 0; k < 16; k++) {
                float2 v = __half22float2(*(__half2*)&raw[ch][k]);
                sx += v.x; sy += v.y;
            }
            red[((ch * 8 + sp) * 64 + jj) * 2 + 0] = sx;
            red[((ch * 8 + sp) * 64 + jj) * 2 + 1] = sy;
        }
    }
    __syncthreads();

    // Combine 8 splits: 384 threads, result fin[ch][128] at red+3072
    if (tid < 384) {
        int ch = tid >> 7, lp = tid & 127;   // lp = jj*2 + comp
        int jj = lp >> 1, comp = lp & 1;
        float s = 0.0f;
        #pragma unroll
        for (int sp = 0; sp < 8; sp++)
            s += red[((ch * 8 + sp) * 64 + jj) * 2 + comp];
        red[3072 + ch * 128 + lp] = s;
    }
    __syncthreads();

    // Decode (j, comp) -> (m, n), normalize, write final output.
    if (tid < 128) {
        int fi = ks * 128 + tid;             // global half index
        int chunk = fi >> 11, rem = fi & 2047;
        int mt = chunk >> 2, nt = chunk & 3;
        int tidm = rem >> 2, c = rem & 3;
        int w = tidm & 31, wid2 = tidm >> 5;
        int quad = w >> 2, tq = w & 3;
        int m = (wid2 & 3) * 32 + mt * 16 + quad + 8 * (c >> 1);
        int n = (wid2 >> 2) * 32 + nt * 8 + 2 * tq + (c & 1);
        int g = n * NG + m;

        float t0 = red[3072 + 0 * 128 + tid];
        float t1 = red[3072 + 1 * 128 + tid];
        float t2 = red[3072 + 2 * 128 + tid];
        float inv = 1.0f / t0;
        out[g]            = t0;
        out[NGNG + g]     = t1 * inv;
        out[2 * NGNG + g] = t2 * inv;
    }
}

extern "C" void kernel_launch(void* const* d_in, const int* in_sizes, int n_in,
                              void* d_out, int out_size) {
    const float* X = (const float*)d_in[0];
    const float* Y = (const float*)d_in[1];
    float* out = (float*)d_out;

    cudaFuncSetAttribute(fused_kernel,
                         cudaFuncAttributeMaxDynamicSharedMemorySize, SMEM_TOTAL);
    fused_kernel<<<KSPLIT, 512, SMEM_TOTAL>>>(X, Y, out);
}